// round 16
// baseline (speedup 1.0000x reference)
#include <cuda_runtime.h>
#include <cuda_fp16.h>
#include <stdint.h>
#include <math.h>

// Problem constants
#define BB   1024
#define LL   77
#define DD   1024
#define HH   16
#define DHH  64
#define DFF  4096

// ---------------- scratch (device globals; no allocation allowed) ----------------
__device__ float  g_mod [BB * 9 * DD];
__device__ float  g_xq  [BB * DD];
__device__ float  g_q   [BB * DD];
__device__ float  g_qw  [BB * HH * DD];

__device__ __half h_silu[BB * DD];
__device__ __half h_m   [BB * DD];
__device__ __half h_t1  [BB * DD];
__device__ __half h_q   [BB * DD];
__device__ __half h_ctxa[BB * HH * DD];
__device__ __half h_h1  [BB * DFF];
__device__ __half h_h2  [BB * DFF];
__device__ __half h_wmod[9 * DD * DD];
__device__ __half h_sawv[DD * DD];
__device__ __half h_sawo[DD * DD];
__device__ __half h_cawq[DD * DD];
__device__ __half h_wkT [DD * DD];
__device__ __half h_cawv[DD * DD];
__device__ __half h_cawo[DD * DD];
__device__ __half h_w1  [DFF * DD];
__device__ __half h_w2  [DFF * DFF];
__device__ __half h_w3  [DD * DFF];

// ---------------- epilogue / output modes ----------------
enum { E_BIAS = 0, E_SCALE = 1, E_GELU = 2, E_RES = 3 };
enum { O_F32 = 1, O_F16 = 2, O_BOTH = 3 };

// ---------------- cp.async / ldmatrix helpers ----------------
__device__ __forceinline__ void cp16(unsigned saddr, const void* g) {
    asm volatile("cp.async.cg.shared.global [%0], [%1], 16;\n" :: "r"(saddr), "l"(g));
}
__device__ __forceinline__ void cp_commit() {
    asm volatile("cp.async.commit_group;\n" ::: "memory");
}
template<int N>
__device__ __forceinline__ void cp_wait() {
    asm volatile("cp.async.wait_group %0;\n" :: "n"(N) : "memory");
}
__device__ __forceinline__ unsigned smem_u32(const void* p) {
    return (unsigned)__cvta_generic_to_shared(p);
}
__device__ __forceinline__ void ldsm4(unsigned addr, unsigned* r) {
    asm volatile("ldmatrix.sync.aligned.m8n8.x4.shared.b16 {%0,%1,%2,%3}, [%4];"
                 : "=r"(r[0]), "=r"(r[1]), "=r"(r[2]), "=r"(r[3]) : "r"(addr));
}

#define HMMA_F16(acc, a, b) \
    asm volatile( \
        "mma.sync.aligned.m16n8k16.row.col.f32.f16.f16.f32 " \
        "{%0,%1,%2,%3}, {%4,%5,%6,%7}, {%8,%9}, {%0,%1,%2,%3};\n" \
        : "+f"((acc)[0]), "+f"((acc)[1]), "+f"((acc)[2]), "+f"((acc)[3]) \
        : "r"((a)[0]), "r"((a)[1]), "r"((a)[2]), "r"((a)[3]), \
          "r"((b)[0]), "r"((b)[1]))

// =====================================================================
// fp16 mma.sync GEMM:  C[M,N] = A[M,K] @ B[N,K]^T (+ epilogue), batched.
// Per-half fragment loading; 2-CTA launch bound. (proven R13 kernel)
// =====================================================================
template<int BM, int BN, int NTHR, int WR, int WC, int STAGES, int EPI, int OUT>
__global__ void __launch_bounds__(NTHR, 2)
hgemm_k(const __half* __restrict__ A, const __half* __restrict__ B,
        const float* __restrict__ bias, float* __restrict__ C,
        __half* __restrict__ C16,
        int K, int lda, int ldb, int ldc,
        long sAo, long sBo, long sBiaso, long sCo,
        const float* __restrict__ res, int ldres,
        const float* __restrict__ alpha, int ldalpha, float scale)
{
    constexpr int BK  = 32;            // halves
    constexpr int SAS = BK + 8;        // 40 halves = 80B
    constexpr int WM  = BM / WR;
    constexpr int WN  = BN / WC;
    constexpr int MF  = WM / 16;
    constexpr int NF  = WN / 8;        // even
    constexpr int CA  = BM * BK / 8 / NTHR;
    constexpr int CB  = BN * BK / 8 / NTHR;
    constexpr int ASZ = BM * SAS;
    constexpr int BSZ = BN * SAS;

    extern __shared__ __half smh[];
    __half* sA = smh;
    __half* sB = smh + STAGES * ASZ;

    A += (long)blockIdx.z * sAo;
    B += (long)blockIdx.z * sBo;
    C += (long)blockIdx.z * sCo;
    if (C16) C16 += (long)blockIdx.z * sCo;
    if (bias) bias += (long)blockIdx.z * sBiaso;

    const int tid  = threadIdx.x;
    const int lane = tid & 31;
    const int warp = tid >> 5;
    const int wr   = warp / WC;
    const int wc   = warp % WC;
    const int m0   = blockIdx.y * BM;
    const int n0   = blockIdx.x * BN;
    const int grp  = lane >> 2;
    const int tg   = lane & 3;

    const unsigned baseA = smem_u32(sA);
    const unsigned baseB = smem_u32(sB);

    const int ltile = lane >> 3, lrl = lane & 7;
    const unsigned offA0 = (unsigned)((wr * WM + lrl + ((ltile & 1) << 3)) * SAS
                                      + ((ltile >> 1) << 3));
    const unsigned offB0 = (unsigned)((wc * WN + ((ltile >> 1) << 3) + lrl) * SAS
                                      + ((ltile & 1) << 3));

    float acc[MF][NF][4];
#pragma unroll
    for (int i = 0; i < MF; i++)
#pragma unroll
        for (int j = 0; j < NF; j++)
#pragma unroll
            for (int r = 0; r < 4; r++) acc[i][j][r] = 0.f;

    const int NT = K / BK;

#pragma unroll
    for (int s = 0; s < STAGES - 1; s++) {
        int k0 = s * BK;
        if (s < NT) {
#pragma unroll
            for (int i = 0; i < CA; i++) {
                int c = tid + i * NTHR, r = c >> 2, q = c & 3;
                cp16(baseA + (unsigned)(s * ASZ + r * SAS + q * 8) * 2,
                     A + (long)(m0 + r) * lda + k0 + q * 8);
            }
#pragma unroll
            for (int i = 0; i < CB; i++) {
                int c = tid + i * NTHR, r = c >> 2, q = c & 3;
                cp16(baseB + (unsigned)(s * BSZ + r * SAS + q * 8) * 2,
                     B + (long)(n0 + r) * ldb + k0 + q * 8);
            }
        }
        cp_commit();
    }

    for (int kt = 0; kt < NT; kt++) {
        cp_wait<STAGES - 2>();
        __syncthreads();

        const unsigned aAddr = baseA + (unsigned)((kt % STAGES) * ASZ) * 2;
        const unsigned bAddr = baseB + (unsigned)((kt % STAGES) * BSZ) * 2;

        unsigned af[MF][4], bf[NF][2];

        // ---- half 0 fragments ----
#pragma unroll
        for (int mi = 0; mi < MF; mi++)
            ldsm4(aAddr + (offA0 + (unsigned)(mi * 16 * SAS)) * 2, af[mi]);
#pragma unroll
        for (int p = 0; p < NF / 2; p++) {
            unsigned r[4];
            ldsm4(bAddr + (offB0 + (unsigned)(p * 16 * SAS)) * 2, r);
            bf[2*p][0]   = r[0];
            bf[2*p][1]   = r[1];
            bf[2*p+1][0] = r[2];
            bf[2*p+1][1] = r[3];
        }

        // ---- issue next-stage cp.async ----
        int nt = kt + STAGES - 1;
        if (nt < NT) {
            int stg = nt % STAGES, k0 = nt * BK;
#pragma unroll
            for (int i = 0; i < CA; i++) {
                int c = tid + i * NTHR, r = c >> 2, q = c & 3;
                cp16(baseA + (unsigned)(stg * ASZ + r * SAS + q * 8) * 2,
                     A + (long)(m0 + r) * lda + k0 + q * 8);
            }
#pragma unroll
            for (int i = 0; i < CB; i++) {
                int c = tid + i * NTHR, r = c >> 2, q = c & 3;
                cp16(baseB + (unsigned)(stg * BSZ + r * SAS + q * 8) * 2,
                     B + (long)(n0 + r) * ldb + k0 + q * 8);
            }
        }
        cp_commit();

        // ---- HMMA half 0 ----
#pragma unroll
        for (int mi = 0; mi < MF; mi++)
#pragma unroll
            for (int ni = 0; ni < NF; ni++)
                HMMA_F16(acc[mi][ni], af[mi], bf[ni]);

        // ---- half 1 fragments ----
#pragma unroll
        for (int mi = 0; mi < MF; mi++)
            ldsm4(aAddr + (offA0 + (unsigned)(mi * 16 * SAS) + 16u) * 2, af[mi]);
#pragma unroll
        for (int p = 0; p < NF / 2; p++) {
            unsigned r[4];
            ldsm4(bAddr + (offB0 + (unsigned)(p * 16 * SAS) + 16u) * 2, r);
            bf[2*p][0]   = r[0];
            bf[2*p][1]   = r[1];
            bf[2*p+1][0] = r[2];
            bf[2*p+1][1] = r[3];
        }

        // ---- HMMA half 1 ----
#pragma unroll
        for (int mi = 0; mi < MF; mi++)
#pragma unroll
            for (int ni = 0; ni < NF; ni++)
                HMMA_F16(acc[mi][ni], af[mi], bf[ni]);
    }

    // ---- epilogue ----
#pragma unroll
    for (int mi = 0; mi < MF; mi++) {
#pragma unroll
        for (int ni = 0; ni < NF; ni++) {
            int mA = m0 + wr * WM + mi * 16 + grp;
            int nA = n0 + wc * WN + ni * 8 + 2 * tg;
            float2 bv = make_float2(0.f, 0.f);
            if (bias) bv = *(const float2*)(bias + nA);
#pragma unroll
            for (int half = 0; half < 2; half++) {
                int m = mA + half * 8;
                float o0 = acc[mi][ni][half * 2 + 0] + bv.x;
                float o1 = acc[mi][ni][half * 2 + 1] + bv.y;
                if (EPI == E_SCALE) { o0 *= scale; o1 *= scale; }
                else if (EPI == E_GELU) {
                    o0 = 0.5f * o0 * (1.f + erff(o0 * 0.70710678118654752f));
                    o1 = 0.5f * o1 * (1.f + erff(o1 * 0.70710678118654752f));
                }
                else if (EPI == E_RES) {
                    float2 rv = *(const float2*)(res + (long)m * ldres + nA);
                    float2 av = *(const float2*)(alpha + (long)m * ldalpha + nA);
                    o0 = rv.x + av.x * o0;
                    o1 = rv.y + av.y * o1;
                }
                if (OUT & O_F32)
                    *(float2*)&C[(long)m * ldc + nA] = make_float2(o0, o1);
                if (OUT & O_F16)
                    *(__half2*)&C16[(long)m * ldc + nA] = __floats2half2_rn(o0, o1);
            }
        }
    }
}

// ---------------- fused fp32 -> fp16 conversion (ALL weights, one launch) ----
#define NJOBS 9
struct F2HJobs {
    const float* src[NJOBS];
    __half*      dst[NJOBS];
    int          start[NJOBS + 1];
};

__global__ void __launch_bounds__(256) f2h_fused_k(F2HJobs jobs) {
    int blk = blockIdx.x;
    int j = 0;
#pragma unroll
    for (int t = 1; t < NJOBS; t++) if (blk >= jobs.start[t]) j = t;
    const float4* src = (const float4*)jobs.src[j];
    uint2*        dst = (uint2*)jobs.dst[j];
    long base = (long)(blk - jobs.start[j]) * 2048 + threadIdx.x;
    float4 a[8];
#pragma unroll
    for (int k = 0; k < 8; k++) a[k] = src[base + k * 256];
#pragma unroll
    for (int k = 0; k < 8; k++) {
        union { __half2 h[2]; uint2 u; } p;
        p.h[0] = __floats2half2_rn(a[k].x, a[k].y);
        p.h[1] = __floats2half2_rn(a[k].z, a[k].w);
        dst[base + k * 256] = p.u;
    }
}

// ---------------- 1024x1024 transpose -> fp16 (for ca_wk) ----------------
__global__ void __launch_bounds__(256)
transpose_h_k(const float* __restrict__ in, __half* __restrict__ out)
{
    __shared__ float t[32][33];
    int bx = blockIdx.x * 32, by = blockIdx.y * 32;
    int x = bx + threadIdx.x;
#pragma unroll
    for (int i = 0; i < 32; i += 8)
        t[threadIdx.y + i][threadIdx.x] = in[(long)(by + threadIdx.y + i) * DD + x];
    __syncthreads();
    x = by + threadIdx.x;
#pragma unroll
    for (int i = 0; i < 32; i += 8)
        out[(long)(bx + threadIdx.y + i) * DD + x] =
            __float2half_rn(t[threadIdx.x][threadIdx.y + i]);
}

// ---------------- silu -> fp16 ----------------
__global__ void silu_k(const float* __restrict__ in, __half* __restrict__ out, int n2) {
    int i = blockIdx.x * blockDim.x + threadIdx.x;
    if (i < n2) {
        float2 v = ((const float2*)in)[i];
        float a = v.x / (1.f + expf(-v.x));
        float b = v.y / (1.f + expf(-v.y));
        ((__half2*)out)[i] = __floats2half2_rn(a, b);
    }
}

// ---------------- block reduce ----------------
__device__ __forceinline__ float blockReduceSum(float v, float* sh) {
    int lane = threadIdx.x & 31, w = threadIdx.x >> 5;
#pragma unroll
    for (int o = 16; o; o >>= 1) v += __shfl_xor_sync(~0u, v, o);
    if (lane == 0) sh[w] = v;
    __syncthreads();
    if (w == 0) {
        v = (lane < 8) ? sh[lane] : 0.f;
#pragma unroll
        for (int o = 4; o; o >>= 1) v += __shfl_xor_sync(~0u, v, o);
        if (lane == 0) sh[0] = v;
    }
    __syncthreads();
    float r = sh[0];
    __syncthreads();
    return r;
}

// ---------------- layernorm + adaLN modulation -> fp16 ----------------
__global__ void __launch_bounds__(256)
ln_mod_k(const float* __restrict__ x, const float* __restrict__ mod,
         int offg, int offb, __half* __restrict__ out)
{
    __shared__ float sh[8];
    int row = blockIdx.x;
    float4 v = ((const float4*)(x + (long)row * DD))[threadIdx.x];
    float tot = blockReduceSum(v.x + v.y + v.z + v.w, sh);
    float mean = tot * (1.f / DD);
    float dx = v.x - mean, dy = v.y - mean, dz = v.z - mean, dw = v.w - mean;
    float tot2 = blockReduceSum(dx*dx + dy*dy + dz*dz + dw*dw, sh);
    float inv = rsqrtf(tot2 * (1.f / DD) + 1e-6f);
    const float* mrow = mod + (long)row * (9*DD);
    float4 g  = *(const float4*)(mrow + offg + threadIdx.x*4);
    float4 be = *(const float4*)(mrow + offb + threadIdx.x*4);
    union { __half2 h[2]; uint2 u; } p;
    p.h[0] = __floats2half2_rn(dx*inv*(1.f+g.x)+be.x, dy*inv*(1.f+g.y)+be.y);
    p.h[1] = __floats2half2_rn(dz*inv*(1.f+g.z)+be.z, dw*inv*(1.f+g.w)+be.w);
    ((uint2*)(out + (long)row * DD))[threadIdx.x] = p.u;
}

// ---------------- cross-attention core: SINGLE-PASS over ctx ----------------
// 4-slot ring buffer, prefetch distance 3: row l+3 is issued at the top of
// iteration l into slot (l+3)&3 (held row l-1, fully consumed before the
// closing barrier of iteration l-1). ~3 iterations of slack vs 577-cyc DRAM
// latency -> latency-hiding instead of BW-starvation.
__global__ void __launch_bounds__(512)
attn_k(const float* __restrict__ ctx,    // [B,L,D] fp32
       const float* __restrict__ qw,     // [B,H,D] fp32 (already scaled by 1/8)
       const float* __restrict__ qs,     // [B,D] fp32 scaled q (for bias term)
       const float* __restrict__ bk,     // [D]
       __half* __restrict__ ctxa)        // [B,H,D] fp16
{
    int b = blockIdx.x;
    int tid = threadIdx.x, lane = tid & 31, w = tid >> 5;   // 16 warps = 16 heads
    __shared__ float s_ctx[4][DD];
    __shared__ float s_p[HH][80];
    __shared__ float s_qb[HH];
    __shared__ float s_inv[HH];

    {   // qb[h] = qs[b, h*64:] . bk[h*64:]
        float v = qs[(long)b*DD + w*DHH + lane]      * bk[w*DHH + lane]
                + qs[(long)b*DD + w*DHH + 32 + lane] * bk[w*DHH + 32 + lane];
#pragma unroll
        for (int o = 16; o; o >>= 1) v += __shfl_xor_sync(~0u, v, o);
        if (lane == 0) s_qb[w] = v;
    }

    const float* ctxb = ctx + (long)b * LL * DD;

    // q row for head w register-resident: 8 float4 per lane
    float4 qv[8];
    {
        const float4* qr = (const float4*)(qw + ((long)b * HH + w) * DD);
#pragma unroll
        for (int i = 0; i < 8; i++) qv[i] = qr[lane + 32 * i];
    }

    // preload rows 0,1,2
    if (tid < 256) {
        ((float4*)s_ctx[0])[tid] = ((const float4*)ctxb)[tid];
        ((float4*)s_ctx[1])[tid] = ((const float4*)(ctxb + DD))[tid];
        ((float4*)s_ctx[2])[tid] = ((const float4*)(ctxb + 2*DD))[tid];
    }
    __syncthreads();

    float acc0[HH], acc1[HH];
#pragma unroll
    for (int h = 0; h < HH; h++) { acc0[h] = 0.f; acc1[h] = 0.f; }

    for (int l = 0; l < LL; l++) {
        int cur = l & 3;

        // prefetch row l+3 into slot (l+3)&3 (== (l-1)&3, consumed last iter)
        if (l + 3 < LL && tid < 256)
            ((float4*)s_ctx[(l + 3) & 3])[tid] =
                ((const float4*)(ctxb + (long)(l + 3) * DD))[tid];

        // score for head w from resident row
        const float4* cs4 = (const float4*)s_ctx[cur];
        float sc = 0.f;
#pragma unroll
        for (int i = 0; i < 8; i++) {
            float4 c = cs4[lane + 32 * i];
            sc += c.x * qv[i].x + c.y * qv[i].y + c.z * qv[i].z + c.w * qv[i].w;
        }
#pragma unroll
        for (int o = 16; o; o >>= 1) sc += __shfl_xor_sync(~0u, sc, o);
        if (lane == 0) s_p[w][l] = expf(sc + s_qb[w]);
        __syncthreads();                 // p ready

        // weighted accumulation from the SAME resident row
        float c0 = s_ctx[cur][tid];
        float c1 = s_ctx[cur][512 + tid];
#pragma unroll
        for (int h = 0; h < HH; h++) {
            float p = s_p[h][l];
            acc0[h] = fmaf(p, c0, acc0[h]);
            acc1[h] = fmaf(p, c1, acc1[h]);
        }
        __syncthreads();                 // row l consumed by all
    }

    {   // 1/sum per head
        float sum = 0.f;
        for (int l = lane; l < LL; l += 32) sum += s_p[w][l];
#pragma unroll
        for (int o = 16; o; o >>= 1) sum += __shfl_xor_sync(~0u, sum, o);
        if (lane == 0) s_inv[w] = 1.f / sum;
    }
    __syncthreads();

    __half* ob = ctxa + (long)b * HH * DD;
#pragma unroll
    for (int h = 0; h < HH; h++) {
        float inv = s_inv[h];
        ob[h*DD + tid]       = __float2half_rn(acc0[h] * inv);
        ob[h*DD + 512 + tid] = __float2half_rn(acc1[h] * inv);
    }
}

// ---------------- host wrapper ----------------
template<int BM, int BN, int NTHR, int WR, int WC, int STAGES, int EPI, int OUT>
static void hgemm(const __half* A, const __half* B, const float* bias,
                  float* C, __half* C16,
                  int M, int N, int K, int lda, int ldb, int ldc,
                  int batch = 1, long sA = 0, long sB = 0, long sBias = 0, long sC = 0,
                  const float* res = nullptr, int ldres = 0,
                  const float* alpha = nullptr, int ldalpha = 0, float scale = 1.f)
{
    constexpr int SMEM = STAGES * (BM + BN) * 40 * 2;
    cudaFuncSetAttribute((const void*)hgemm_k<BM,BN,NTHR,WR,WC,STAGES,EPI,OUT>,
                         cudaFuncAttributeMaxDynamicSharedMemorySize, SMEM);
    dim3 g(N / BN, M / BM, batch);
    hgemm_k<BM,BN,NTHR,WR,WC,STAGES,EPI,OUT><<<g, NTHR, SMEM>>>(
        A, B, bias, C, C16, K, lda, ldb, ldc, sA, sB, sBias, sC,
        res, ldres, alpha, ldalpha, scale);
}

// cfg B: 128x128 tile, 256 thr (2x4 warps, warp tile 64x32), 3 stages
#define GEMM_B(EPI, OUT) hgemm<128,128,256,2,4,3,EPI,OUT>
// cfg S: 64x64 tile, 128 thr, 4 stages
#define GEMM_S(EPI, OUT) hgemm<64,64,128,2,2,4,EPI,OUT>

extern "C" void kernel_launch(void* const* d_in, const int* in_sizes, int n_in,
                              void* d_out, int out_size)
{
    (void)in_sizes; (void)n_in; (void)out_size;
    const float* x      = (const float*)d_in[0];
    const float* t_emb  = (const float*)d_in[1];
    const float* ctx    = (const float*)d_in[2];
    const float* w_mod  = (const float*)d_in[4];
    const float* b_mod  = (const float*)d_in[5];
    const float* sa_wv  = (const float*)d_in[10];
    const float* sa_bv  = (const float*)d_in[11];
    const float* sa_wo  = (const float*)d_in[12];
    const float* sa_bo  = (const float*)d_in[13];
    const float* ca_wq  = (const float*)d_in[14];
    const float* ca_bq  = (const float*)d_in[15];
    const float* ca_wk  = (const float*)d_in[16];
    const float* ca_bk  = (const float*)d_in[17];
    const float* ca_wv  = (const float*)d_in[18];
    const float* ca_bv  = (const float*)d_in[19];
    const float* ca_wo  = (const float*)d_in[20];
    const float* ca_bo  = (const float*)d_in[21];
    const float* w1     = (const float*)d_in[22];
    const float* b1     = (const float*)d_in[23];
    const float* w2     = (const float*)d_in[24];
    const float* b2     = (const float*)d_in[25];
    const float* w3     = (const float*)d_in[26];
    const float* b3     = (const float*)d_in[27];
    float* out = (float*)d_out;

    float *pmod, *pxq, *pq, *pqw;
    __half *ph_silu, *ph_m, *ph_t1, *ph_q, *ph_ctxa, *ph_h1, *ph_h2;
    __half *ph_wmod, *ph_sawv, *ph_sawo, *ph_cawq, *ph_wkT, *ph_cawv, *ph_cawo;
    __half *ph_w1, *ph_w2, *ph_w3;
    cudaGetSymbolAddress((void**)&pmod,    g_mod);
    cudaGetSymbolAddress((void**)&pxq,     g_xq);
    cudaGetSymbolAddress((void**)&pq,      g_q);
    cudaGetSymbolAddress((void**)&pqw,     g_qw);
    cudaGetSymbolAddress((void**)&ph_silu, h_silu);
    cudaGetSymbolAddress((void**)&ph_m,    h_m);
    cudaGetSymbolAddress((void**)&ph_t1,   h_t1);
    cudaGetSymbolAddress((void**)&ph_q,    h_q);
    cudaGetSymbolAddress((void**)&ph_ctxa, h_ctxa);
    cudaGetSymbolAddress((void**)&ph_h1,   h_h1);
    cudaGetSymbolAddress((void**)&ph_h2,   h_h2);
    cudaGetSymbolAddress((void**)&ph_wmod, h_wmod);
    cudaGetSymbolAddress((void**)&ph_sawv, h_sawv);
    cudaGetSymbolAddress((void**)&ph_sawo, h_sawo);
    cudaGetSymbolAddress((void**)&ph_cawq, h_cawq);
    cudaGetSymbolAddress((void**)&ph_wkT,  h_wkT);
    cudaGetSymbolAddress((void**)&ph_cawv, h_cawv);
    cudaGetSymbolAddress((void**)&ph_cawo, h_cawo);
    cudaGetSymbolAddress((void**)&ph_w1,   h_w1);
    cudaGetSymbolAddress((void**)&ph_w2,   h_w2);
    cudaGetSymbolAddress((void**)&ph_w3,   h_w3);

    // 0. ALL weight conversions in one launch (full-chip, DRAM-bound)
    {
        F2HJobs jobs;
        const float* srcs[NJOBS] = { w_mod, sa_wv, sa_wo, ca_wq, ca_wv, ca_wo,
                                     w1, w2, w3 };
        __half* dsts[NJOBS] = { ph_wmod, ph_sawv, ph_sawo, ph_cawq, ph_cawv,
                                ph_cawo, ph_w1, ph_w2, ph_w3 };
        long sizes[NJOBS] = { 9L*DD*DD, (long)DD*DD, (long)DD*DD, (long)DD*DD,
                              (long)DD*DD, (long)DD*DD,
                              (long)DFF*DD, (long)DFF*DFF, (long)DD*DFF };
        int cum = 0;
        for (int j = 0; j < NJOBS; j++) {
            jobs.src[j] = srcs[j];
            jobs.dst[j] = dsts[j];
            jobs.start[j] = cum;
            cum += (int)(sizes[j] / 8192);
        }
        jobs.start[NJOBS] = cum;
        f2h_fused_k<<<cum, 256>>>(jobs);
    }
    transpose_h_k<<<dim3(32,32), dim3(32,8)>>>(ca_wk, ph_wkT);

    // 1. silu(t_emb) -> fp16
    silu_k<<<(BB*DD/2)/256, 256>>>(t_emb, ph_silu, BB*DD/2);

    // 2. mod = silu(t_emb) @ w_mod^T + b_mod   [1024, 9216] fp32
    GEMM_B(E_BIAS, O_F32)(ph_silu, ph_wmod, b_mod, pmod, nullptr,
                          BB, 9*DD, DD, DD, DD, 9*DD);

    // 3. m1 = ln(x)*(1+g1)+be1 -> fp16
    ln_mod_k<<<BB, 256>>>(x, pmod, 0*DD, 1*DD, ph_m);

    // 4. t1 = m1 @ sa_wv^T + sa_bv -> fp16
    GEMM_S(E_BIAS, O_F16)(ph_m, ph_sawv, sa_bv, nullptr, ph_t1,
                          BB, DD, DD, DD, DD, DD);

    // 5. x_q = x + a1 * (t1 @ sa_wo^T + sa_bo) -> fp32
    GEMM_S(E_RES, O_F32)(ph_t1, ph_sawo, sa_bo, pxq, nullptr,
                         BB, DD, DD, DD, DD, DD,
                         1, 0, 0, 0, 0, x, DD, pmod + 2*DD, 9*DD);

    // 6. m2 -> fp16
    ln_mod_k<<<BB, 256>>>(pxq, pmod, 3*DD, 4*DD, ph_m);

    // 7. q = (m2 @ ca_wq^T + ca_bq) / 8 -> fp32 + fp16
    GEMM_S(E_SCALE, O_BOTH)(ph_m, ph_cawq, ca_bq, pq, ph_q,
                            BB, DD, DD, DD, DD, DD,
                            1, 0, 0, 0, 0, nullptr, 0, nullptr, 0, 0.125f);

    // 8. qw[b,h,d] = sum_j q[b,h*64+j] * wkT[d,h*64+j]  (batched) -> fp32
    GEMM_S(E_BIAS, O_F32)(ph_q, ph_wkT, nullptr, pqw, nullptr,
                          BB, DD, DHH, DD, DD, HH*DD,
                          HH, DHH, DHH, 0, DD);

    // 9. attention (single-pass, distance-3 prefetch) -> ctxa fp16
    attn_k<<<BB, 512>>>(ctx, pqw, pq, ca_bk, ph_ctxa);

    // 10. ao = ctxa @ ca_wv^T + ca_bv  (batched heads) -> fp16
    GEMM_S(E_BIAS, O_F16)(ph_ctxa, ph_cawv, ca_bv, nullptr, ph_t1,
                          BB, DHH, DD, HH*DD, DD, DD,
                          HH, DD, (long)DHH*DD, DHH, DHH);

    // 11. x_q = x_q + a2 * (ao @ ca_wo^T + ca_bo) -> fp32
    GEMM_S(E_RES, O_F32)(ph_t1, ph_cawo, ca_bo, pxq, nullptr,
                         BB, DD, DD, DD, DD, DD,
                         1, 0, 0, 0, 0, pxq, DD, pmod + 5*DD, 9*DD);

    // 12. m3 -> fp16
    ln_mod_k<<<BB, 256>>>(pxq, pmod, 6*DD, 7*DD, ph_m);

    // 13. h1 = gelu(m3 @ w1^T + b1) -> fp16
    GEMM_B(E_GELU, O_F16)(ph_m, ph_w1, b1, nullptr, ph_h1,
                          BB, DFF, DD, DD, DD, DFF);

    // 14. h2 = gelu(h1 @ w2^T + b2) -> fp16
    GEMM_B(E_GELU, O_F16)(ph_h1, ph_w2, b2, nullptr, ph_h2,
                          BB, DFF, DFF, DFF, DFF, DFF);

    // 15. out = x_q + a3 * (h2 @ w3^T + b3) -> fp32
    GEMM_S(E_RES, O_F32)(ph_h2, ph_w3, b3, out, nullptr,
                         BB, DD, DFF, DFF, DFF, DD,
                         1, 0, 0, 0, 0, pxq, DD, pmod + 8*DD, 9*DD);
}

// round 17
// speedup vs baseline: 1.1899x; 1.1899x over previous
#include <cuda_runtime.h>
#include <cuda_fp16.h>
#include <stdint.h>
#include <math.h>

// Problem constants
#define BB   1024
#define LL   77
#define DD   1024
#define HH   16
#define DHH  64
#define DFF  4096

// ---------------- scratch (device globals; no allocation allowed) ----------------
__device__ float  g_mod [BB * 9 * DD];
__device__ float  g_xq  [BB * DD];
__device__ float  g_q   [BB * DD];
__device__ float  g_qw  [BB * HH * DD];

__device__ __half h_silu[BB * DD];
__device__ __half h_m   [BB * DD];
__device__ __half h_t1  [BB * DD];
__device__ __half h_q   [BB * DD];
__device__ __half h_ctxa[BB * HH * DD];
__device__ __half h_h1  [BB * DFF];
__device__ __half h_h2  [BB * DFF];
__device__ __half h_wmod[9 * DD * DD];
__device__ __half h_sawv[DD * DD];
__device__ __half h_sawo[DD * DD];
__device__ __half h_cawq[DD * DD];
__device__ __half h_wkT [DD * DD];
__device__ __half h_cawv[DD * DD];
__device__ __half h_cawo[DD * DD];
__device__ __half h_w1  [DFF * DD];
__device__ __half h_w2  [DFF * DFF];
__device__ __half h_w3  [DD * DFF];

// ---------------- epilogue / output modes ----------------
enum { E_BIAS = 0, E_SCALE = 1, E_GELU = 2, E_RES = 3 };
enum { O_F32 = 1, O_F16 = 2, O_BOTH = 3 };

// ---------------- cp.async / ldmatrix helpers ----------------
__device__ __forceinline__ void cp16(unsigned saddr, const void* g) {
    asm volatile("cp.async.cg.shared.global [%0], [%1], 16;\n" :: "r"(saddr), "l"(g));
}
__device__ __forceinline__ void cp_commit() {
    asm volatile("cp.async.commit_group;\n" ::: "memory");
}
template<int N>
__device__ __forceinline__ void cp_wait() {
    asm volatile("cp.async.wait_group %0;\n" :: "n"(N) : "memory");
}
__device__ __forceinline__ unsigned smem_u32(const void* p) {
    return (unsigned)__cvta_generic_to_shared(p);
}
__device__ __forceinline__ void ldsm4(unsigned addr, unsigned* r) {
    asm volatile("ldmatrix.sync.aligned.m8n8.x4.shared.b16 {%0,%1,%2,%3}, [%4];"
                 : "=r"(r[0]), "=r"(r[1]), "=r"(r[2]), "=r"(r[3]) : "r"(addr));
}

#define HMMA_F16(acc, a, b) \
    asm volatile( \
        "mma.sync.aligned.m16n8k16.row.col.f32.f16.f16.f32 " \
        "{%0,%1,%2,%3}, {%4,%5,%6,%7}, {%8,%9}, {%0,%1,%2,%3};\n" \
        : "+f"((acc)[0]), "+f"((acc)[1]), "+f"((acc)[2]), "+f"((acc)[3]) \
        : "r"((a)[0]), "r"((a)[1]), "r"((a)[2]), "r"((a)[3]), \
          "r"((b)[0]), "r"((b)[1]))

// =====================================================================
// fp16 mma.sync GEMM:  C[M,N] = A[M,K] @ B[N,K]^T (+ epilogue), batched.
// Per-half fragment loading; 2-CTA launch bound. (proven R13 kernel)
// =====================================================================
template<int BM, int BN, int NTHR, int WR, int WC, int STAGES, int EPI, int OUT>
__global__ void __launch_bounds__(NTHR, 2)
hgemm_k(const __half* __restrict__ A, const __half* __restrict__ B,
        const float* __restrict__ bias, float* __restrict__ C,
        __half* __restrict__ C16,
        int K, int lda, int ldb, int ldc,
        long sAo, long sBo, long sBiaso, long sCo,
        const float* __restrict__ res, int ldres,
        const float* __restrict__ alpha, int ldalpha, float scale)
{
    constexpr int BK  = 32;            // halves
    constexpr int SAS = BK + 8;        // 40 halves = 80B
    constexpr int WM  = BM / WR;
    constexpr int WN  = BN / WC;
    constexpr int MF  = WM / 16;
    constexpr int NF  = WN / 8;        // even
    constexpr int CA  = BM * BK / 8 / NTHR;
    constexpr int CB  = BN * BK / 8 / NTHR;
    constexpr int ASZ = BM * SAS;
    constexpr int BSZ = BN * SAS;

    extern __shared__ __half smh[];
    __half* sA = smh;
    __half* sB = smh + STAGES * ASZ;

    A += (long)blockIdx.z * sAo;
    B += (long)blockIdx.z * sBo;
    C += (long)blockIdx.z * sCo;
    if (C16) C16 += (long)blockIdx.z * sCo;
    if (bias) bias += (long)blockIdx.z * sBiaso;

    const int tid  = threadIdx.x;
    const int lane = tid & 31;
    const int warp = tid >> 5;
    const int wr   = warp / WC;
    const int wc   = warp % WC;
    const int m0   = blockIdx.y * BM;
    const int n0   = blockIdx.x * BN;
    const int grp  = lane >> 2;
    const int tg   = lane & 3;

    const unsigned baseA = smem_u32(sA);
    const unsigned baseB = smem_u32(sB);

    const int ltile = lane >> 3, lrl = lane & 7;
    const unsigned offA0 = (unsigned)((wr * WM + lrl + ((ltile & 1) << 3)) * SAS
                                      + ((ltile >> 1) << 3));
    const unsigned offB0 = (unsigned)((wc * WN + ((ltile >> 1) << 3) + lrl) * SAS
                                      + ((ltile & 1) << 3));

    float acc[MF][NF][4];
#pragma unroll
    for (int i = 0; i < MF; i++)
#pragma unroll
        for (int j = 0; j < NF; j++)
#pragma unroll
            for (int r = 0; r < 4; r++) acc[i][j][r] = 0.f;

    const int NT = K / BK;

#pragma unroll
    for (int s = 0; s < STAGES - 1; s++) {
        int k0 = s * BK;
        if (s < NT) {
#pragma unroll
            for (int i = 0; i < CA; i++) {
                int c = tid + i * NTHR, r = c >> 2, q = c & 3;
                cp16(baseA + (unsigned)(s * ASZ + r * SAS + q * 8) * 2,
                     A + (long)(m0 + r) * lda + k0 + q * 8);
            }
#pragma unroll
            for (int i = 0; i < CB; i++) {
                int c = tid + i * NTHR, r = c >> 2, q = c & 3;
                cp16(baseB + (unsigned)(s * BSZ + r * SAS + q * 8) * 2,
                     B + (long)(n0 + r) * ldb + k0 + q * 8);
            }
        }
        cp_commit();
    }

    for (int kt = 0; kt < NT; kt++) {
        cp_wait<STAGES - 2>();
        __syncthreads();

        const unsigned aAddr = baseA + (unsigned)((kt % STAGES) * ASZ) * 2;
        const unsigned bAddr = baseB + (unsigned)((kt % STAGES) * BSZ) * 2;

        unsigned af[MF][4], bf[NF][2];

        // ---- half 0 fragments ----
#pragma unroll
        for (int mi = 0; mi < MF; mi++)
            ldsm4(aAddr + (offA0 + (unsigned)(mi * 16 * SAS)) * 2, af[mi]);
#pragma unroll
        for (int p = 0; p < NF / 2; p++) {
            unsigned r[4];
            ldsm4(bAddr + (offB0 + (unsigned)(p * 16 * SAS)) * 2, r);
            bf[2*p][0]   = r[0];
            bf[2*p][1]   = r[1];
            bf[2*p+1][0] = r[2];
            bf[2*p+1][1] = r[3];
        }

        // ---- issue next-stage cp.async ----
        int nt = kt + STAGES - 1;
        if (nt < NT) {
            int stg = nt % STAGES, k0 = nt * BK;
#pragma unroll
            for (int i = 0; i < CA; i++) {
                int c = tid + i * NTHR, r = c >> 2, q = c & 3;
                cp16(baseA + (unsigned)(stg * ASZ + r * SAS + q * 8) * 2,
                     A + (long)(m0 + r) * lda + k0 + q * 8);
            }
#pragma unroll
            for (int i = 0; i < CB; i++) {
                int c = tid + i * NTHR, r = c >> 2, q = c & 3;
                cp16(baseB + (unsigned)(stg * BSZ + r * SAS + q * 8) * 2,
                     B + (long)(n0 + r) * ldb + k0 + q * 8);
            }
        }
        cp_commit();

        // ---- HMMA half 0 ----
#pragma unroll
        for (int mi = 0; mi < MF; mi++)
#pragma unroll
            for (int ni = 0; ni < NF; ni++)
                HMMA_F16(acc[mi][ni], af[mi], bf[ni]);

        // ---- half 1 fragments ----
#pragma unroll
        for (int mi = 0; mi < MF; mi++)
            ldsm4(aAddr + (offA0 + (unsigned)(mi * 16 * SAS) + 16u) * 2, af[mi]);
#pragma unroll
        for (int p = 0; p < NF / 2; p++) {
            unsigned r[4];
            ldsm4(bAddr + (offB0 + (unsigned)(p * 16 * SAS) + 16u) * 2, r);
            bf[2*p][0]   = r[0];
            bf[2*p][1]   = r[1];
            bf[2*p+1][0] = r[2];
            bf[2*p+1][1] = r[3];
        }

        // ---- HMMA half 1 ----
#pragma unroll
        for (int mi = 0; mi < MF; mi++)
#pragma unroll
            for (int ni = 0; ni < NF; ni++)
                HMMA_F16(acc[mi][ni], af[mi], bf[ni]);
    }

    // ---- epilogue ----
#pragma unroll
    for (int mi = 0; mi < MF; mi++) {
#pragma unroll
        for (int ni = 0; ni < NF; ni++) {
            int mA = m0 + wr * WM + mi * 16 + grp;
            int nA = n0 + wc * WN + ni * 8 + 2 * tg;
            float2 bv = make_float2(0.f, 0.f);
            if (bias) bv = *(const float2*)(bias + nA);
#pragma unroll
            for (int half = 0; half < 2; half++) {
                int m = mA + half * 8;
                float o0 = acc[mi][ni][half * 2 + 0] + bv.x;
                float o1 = acc[mi][ni][half * 2 + 1] + bv.y;
                if (EPI == E_SCALE) { o0 *= scale; o1 *= scale; }
                else if (EPI == E_GELU) {
                    o0 = 0.5f * o0 * (1.f + erff(o0 * 0.70710678118654752f));
                    o1 = 0.5f * o1 * (1.f + erff(o1 * 0.70710678118654752f));
                }
                else if (EPI == E_RES) {
                    float2 rv = *(const float2*)(res + (long)m * ldres + nA);
                    float2 av = *(const float2*)(alpha + (long)m * ldalpha + nA);
                    o0 = rv.x + av.x * o0;
                    o1 = rv.y + av.y * o1;
                }
                if (OUT & O_F32)
                    *(float2*)&C[(long)m * ldc + nA] = make_float2(o0, o1);
                if (OUT & O_F16)
                    *(__half2*)&C16[(long)m * ldc + nA] = __floats2half2_rn(o0, o1);
            }
        }
    }
}

// ---------------- fused fp32 -> fp16 conversion (ALL weights, one launch) ----
#define NJOBS 9
struct F2HJobs {
    const float* src[NJOBS];
    __half*      dst[NJOBS];
    int          start[NJOBS + 1];
};

__global__ void __launch_bounds__(256) f2h_fused_k(F2HJobs jobs) {
    int blk = blockIdx.x;
    int j = 0;
#pragma unroll
    for (int t = 1; t < NJOBS; t++) if (blk >= jobs.start[t]) j = t;
    const float4* src = (const float4*)jobs.src[j];
    uint2*        dst = (uint2*)jobs.dst[j];
    long base = (long)(blk - jobs.start[j]) * 2048 + threadIdx.x;
    float4 a[8];
#pragma unroll
    for (int k = 0; k < 8; k++) a[k] = src[base + k * 256];
#pragma unroll
    for (int k = 0; k < 8; k++) {
        union { __half2 h[2]; uint2 u; } p;
        p.h[0] = __floats2half2_rn(a[k].x, a[k].y);
        p.h[1] = __floats2half2_rn(a[k].z, a[k].w);
        dst[base + k * 256] = p.u;
    }
}

// ---------------- 1024x1024 transpose -> fp16 (for ca_wk) ----------------
__global__ void __launch_bounds__(256)
transpose_h_k(const float* __restrict__ in, __half* __restrict__ out)
{
    __shared__ float t[32][33];
    int bx = blockIdx.x * 32, by = blockIdx.y * 32;
    int x = bx + threadIdx.x;
#pragma unroll
    for (int i = 0; i < 32; i += 8)
        t[threadIdx.y + i][threadIdx.x] = in[(long)(by + threadIdx.y + i) * DD + x];
    __syncthreads();
    x = by + threadIdx.x;
#pragma unroll
    for (int i = 0; i < 32; i += 8)
        out[(long)(bx + threadIdx.y + i) * DD + x] =
            __float2half_rn(t[threadIdx.x][threadIdx.y + i]);
}

// ---------------- silu -> fp16 ----------------
__global__ void silu_k(const float* __restrict__ in, __half* __restrict__ out, int n2) {
    int i = blockIdx.x * blockDim.x + threadIdx.x;
    if (i < n2) {
        float2 v = ((const float2*)in)[i];
        float a = v.x / (1.f + expf(-v.x));
        float b = v.y / (1.f + expf(-v.y));
        ((__half2*)out)[i] = __floats2half2_rn(a, b);
    }
}

// ---------------- block reduce ----------------
__device__ __forceinline__ float blockReduceSum(float v, float* sh) {
    int lane = threadIdx.x & 31, w = threadIdx.x >> 5;
#pragma unroll
    for (int o = 16; o; o >>= 1) v += __shfl_xor_sync(~0u, v, o);
    if (lane == 0) sh[w] = v;
    __syncthreads();
    if (w == 0) {
        v = (lane < 8) ? sh[lane] : 0.f;
#pragma unroll
        for (int o = 4; o; o >>= 1) v += __shfl_xor_sync(~0u, v, o);
        if (lane == 0) sh[0] = v;
    }
    __syncthreads();
    float r = sh[0];
    __syncthreads();
    return r;
}

// ---------------- layernorm + adaLN modulation -> fp16 ----------------
__global__ void __launch_bounds__(256)
ln_mod_k(const float* __restrict__ x, const float* __restrict__ mod,
         int offg, int offb, __half* __restrict__ out)
{
    __shared__ float sh[8];
    int row = blockIdx.x;
    float4 v = ((const float4*)(x + (long)row * DD))[threadIdx.x];
    float tot = blockReduceSum(v.x + v.y + v.z + v.w, sh);
    float mean = tot * (1.f / DD);
    float dx = v.x - mean, dy = v.y - mean, dz = v.z - mean, dw = v.w - mean;
    float tot2 = blockReduceSum(dx*dx + dy*dy + dz*dz + dw*dw, sh);
    float inv = rsqrtf(tot2 * (1.f / DD) + 1e-6f);
    const float* mrow = mod + (long)row * (9*DD);
    float4 g  = *(const float4*)(mrow + offg + threadIdx.x*4);
    float4 be = *(const float4*)(mrow + offb + threadIdx.x*4);
    union { __half2 h[2]; uint2 u; } p;
    p.h[0] = __floats2half2_rn(dx*inv*(1.f+g.x)+be.x, dy*inv*(1.f+g.y)+be.y);
    p.h[1] = __floats2half2_rn(dz*inv*(1.f+g.z)+be.z, dw*inv*(1.f+g.w)+be.w);
    ((uint2*)(out + (long)row * DD))[threadIdx.x] = p.u;
}

// ---------------- cross-attention core: SINGLE-PASS over ctx ----------------
// 4-slot ring, 3 rows in flight via cp.async (completion tracked by
// wait_group, so issuing threads never stall on DRAM latency).
// Per iteration: wait row l -> sync -> issue row l+3 (async) -> score ->
// sync -> accumulate. Slot (l+3)&3 was consumed in iter l-1; the top
// barrier of iter l orders its reuse.
__global__ void __launch_bounds__(512)
attn_k(const float* __restrict__ ctx,    // [B,L,D] fp32
       const float* __restrict__ qw,     // [B,H,D] fp32 (already scaled by 1/8)
       const float* __restrict__ qs,     // [B,D] fp32 scaled q (for bias term)
       const float* __restrict__ bk,     // [D]
       __half* __restrict__ ctxa)        // [B,H,D] fp16
{
    int b = blockIdx.x;
    int tid = threadIdx.x, lane = tid & 31, w = tid >> 5;   // 16 warps = 16 heads
    __shared__ float s_ctx[4][DD];
    __shared__ float s_p[HH][80];
    __shared__ float s_qb[HH];
    __shared__ float s_inv[HH];

    {   // qb[h] = qs[b, h*64:] . bk[h*64:]
        float v = qs[(long)b*DD + w*DHH + lane]      * bk[w*DHH + lane]
                + qs[(long)b*DD + w*DHH + 32 + lane] * bk[w*DHH + 32 + lane];
#pragma unroll
        for (int o = 16; o; o >>= 1) v += __shfl_xor_sync(~0u, v, o);
        if (lane == 0) s_qb[w] = v;
    }

    const float* ctxb = ctx + (long)b * LL * DD;
    const unsigned sbase = smem_u32(s_ctx);

    // q row for head w register-resident: 8 float4 per lane
    float4 qv[8];
    {
        const float4* qr = (const float4*)(qw + ((long)b * HH + w) * DD);
#pragma unroll
        for (int i = 0; i < 8; i++) qv[i] = qr[lane + 32 * i];
    }

    // prologue: rows 0,1,2 via cp.async, one commit group per row
#pragma unroll
    for (int s = 0; s < 3; s++) {
        if (tid < 256)
            cp16(sbase + (unsigned)(s * DD + tid * 4) * 4,
                 ctxb + (long)s * DD + tid * 4);
        cp_commit();
    }

    float acc0[HH], acc1[HH];
#pragma unroll
    for (int h = 0; h < HH; h++) { acc0[h] = 0.f; acc1[h] = 0.f; }

    for (int l = 0; l < LL; l++) {
        int cur = l & 3;

        cp_wait<2>();                    // row l complete (<=2 groups pending)
        __syncthreads();                 // visible to all; prev slot consumed

        // issue row l+3 into slot (l+3)&3 (async; no stall)
        if (l + 3 < LL && tid < 256)
            cp16(sbase + (unsigned)(((l + 3) & 3) * DD + tid * 4) * 4,
                 ctxb + (long)(l + 3) * DD + tid * 4);
        cp_commit();

        // score for head w from resident row
        const float4* cs4 = (const float4*)s_ctx[cur];
        float sc = 0.f;
#pragma unroll
        for (int i = 0; i < 8; i++) {
            float4 c = cs4[lane + 32 * i];
            sc += c.x * qv[i].x + c.y * qv[i].y + c.z * qv[i].z + c.w * qv[i].w;
        }
#pragma unroll
        for (int o = 16; o; o >>= 1) sc += __shfl_xor_sync(~0u, sc, o);
        if (lane == 0) s_p[w][l] = expf(sc + s_qb[w]);
        __syncthreads();                 // p ready

        // weighted accumulation from the SAME resident row
        float c0 = s_ctx[cur][tid];
        float c1 = s_ctx[cur][512 + tid];
#pragma unroll
        for (int h = 0; h < HH; h++) {
            float p = s_p[h][l];
            acc0[h] = fmaf(p, c0, acc0[h]);
            acc1[h] = fmaf(p, c1, acc1[h]);
        }
        // (no closing barrier: next iteration's top barrier orders reuse)
    }

    __syncthreads();
    {   // 1/sum per head
        float sum = 0.f;
        for (int l = lane; l < LL; l += 32) sum += s_p[w][l];
#pragma unroll
        for (int o = 16; o; o >>= 1) sum += __shfl_xor_sync(~0u, sum, o);
        if (lane == 0) s_inv[w] = 1.f / sum;
    }
    __syncthreads();

    __half* ob = ctxa + (long)b * HH * DD;
#pragma unroll
    for (int h = 0; h < HH; h++) {
        float inv = s_inv[h];
        ob[h*DD + tid]       = __float2half_rn(acc0[h] * inv);
        ob[h*DD + 512 + tid] = __float2half_rn(acc1[h] * inv);
    }
}

// ---------------- host wrapper ----------------
template<int BM, int BN, int NTHR, int WR, int WC, int STAGES, int EPI, int OUT>
static void hgemm(const __half* A, const __half* B, const float* bias,
                  float* C, __half* C16,
                  int M, int N, int K, int lda, int ldb, int ldc,
                  int batch = 1, long sA = 0, long sB = 0, long sBias = 0, long sC = 0,
                  const float* res = nullptr, int ldres = 0,
                  const float* alpha = nullptr, int ldalpha = 0, float scale = 1.f)
{
    constexpr int SMEM = STAGES * (BM + BN) * 40 * 2;
    cudaFuncSetAttribute((const void*)hgemm_k<BM,BN,NTHR,WR,WC,STAGES,EPI,OUT>,
                         cudaFuncAttributeMaxDynamicSharedMemorySize, SMEM);
    dim3 g(N / BN, M / BM, batch);
    hgemm_k<BM,BN,NTHR,WR,WC,STAGES,EPI,OUT><<<g, NTHR, SMEM>>>(
        A, B, bias, C, C16, K, lda, ldb, ldc, sA, sB, sBias, sC,
        res, ldres, alpha, ldalpha, scale);
}

// cfg B: 128x128 tile, 256 thr (2x4 warps, warp tile 64x32), 3 stages
#define GEMM_B(EPI, OUT) hgemm<128,128,256,2,4,3,EPI,OUT>
// cfg S: 64x64 tile, 128 thr, 4 stages
#define GEMM_S(EPI, OUT) hgemm<64,64,128,2,2,4,EPI,OUT>

extern "C" void kernel_launch(void* const* d_in, const int* in_sizes, int n_in,
                              void* d_out, int out_size)
{
    (void)in_sizes; (void)n_in; (void)out_size;
    const float* x      = (const float*)d_in[0];
    const float* t_emb  = (const float*)d_in[1];
    const float* ctx    = (const float*)d_in[2];
    const float* w_mod  = (const float*)d_in[4];
    const float* b_mod  = (const float*)d_in[5];
    const float* sa_wv  = (const float*)d_in[10];
    const float* sa_bv  = (const float*)d_in[11];
    const float* sa_wo  = (const float*)d_in[12];
    const float* sa_bo  = (const float*)d_in[13];
    const float* ca_wq  = (const float*)d_in[14];
    const float* ca_bq  = (const float*)d_in[15];
    const float* ca_wk  = (const float*)d_in[16];
    const float* ca_bk  = (const float*)d_in[17];
    const float* ca_wv  = (const float*)d_in[18];
    const float* ca_bv  = (const float*)d_in[19];
    const float* ca_wo  = (const float*)d_in[20];
    const float* ca_bo  = (const float*)d_in[21];
    const float* w1     = (const float*)d_in[22];
    const float* b1     = (const float*)d_in[23];
    const float* w2     = (const float*)d_in[24];
    const float* b2     = (const float*)d_in[25];
    const float* w3     = (const float*)d_in[26];
    const float* b3     = (const float*)d_in[27];
    float* out = (float*)d_out;

    float *pmod, *pxq, *pq, *pqw;
    __half *ph_silu, *ph_m, *ph_t1, *ph_q, *ph_ctxa, *ph_h1, *ph_h2;
    __half *ph_wmod, *ph_sawv, *ph_sawo, *ph_cawq, *ph_wkT, *ph_cawv, *ph_cawo;
    __half *ph_w1, *ph_w2, *ph_w3;
    cudaGetSymbolAddress((void**)&pmod,    g_mod);
    cudaGetSymbolAddress((void**)&pxq,     g_xq);
    cudaGetSymbolAddress((void**)&pq,      g_q);
    cudaGetSymbolAddress((void**)&pqw,     g_qw);
    cudaGetSymbolAddress((void**)&ph_silu, h_silu);
    cudaGetSymbolAddress((void**)&ph_m,    h_m);
    cudaGetSymbolAddress((void**)&ph_t1,   h_t1);
    cudaGetSymbolAddress((void**)&ph_q,    h_q);
    cudaGetSymbolAddress((void**)&ph_ctxa, h_ctxa);
    cudaGetSymbolAddress((void**)&ph_h1,   h_h1);
    cudaGetSymbolAddress((void**)&ph_h2,   h_h2);
    cudaGetSymbolAddress((void**)&ph_wmod, h_wmod);
    cudaGetSymbolAddress((void**)&ph_sawv, h_sawv);
    cudaGetSymbolAddress((void**)&ph_sawo, h_sawo);
    cudaGetSymbolAddress((void**)&ph_cawq, h_cawq);
    cudaGetSymbolAddress((void**)&ph_wkT,  h_wkT);
    cudaGetSymbolAddress((void**)&ph_cawv, h_cawv);
    cudaGetSymbolAddress((void**)&ph_cawo, h_cawo);
    cudaGetSymbolAddress((void**)&ph_w1,   h_w1);
    cudaGetSymbolAddress((void**)&ph_w2,   h_w2);
    cudaGetSymbolAddress((void**)&ph_w3,   h_w3);

    // 0. ALL weight conversions in one launch (full-chip, DRAM-bound)
    {
        F2HJobs jobs;
        const float* srcs[NJOBS] = { w_mod, sa_wv, sa_wo, ca_wq, ca_wv, ca_wo,
                                     w1, w2, w3 };
        __half* dsts[NJOBS] = { ph_wmod, ph_sawv, ph_sawo, ph_cawq, ph_cawv,
                                ph_cawo, ph_w1, ph_w2, ph_w3 };
        long sizes[NJOBS] = { 9L*DD*DD, (long)DD*DD, (long)DD*DD, (long)DD*DD,
                              (long)DD*DD, (long)DD*DD,
                              (long)DFF*DD, (long)DFF*DFF, (long)DD*DFF };
        int cum = 0;
        for (int j = 0; j < NJOBS; j++) {
            jobs.src[j] = srcs[j];
            jobs.dst[j] = dsts[j];
            jobs.start[j] = cum;
            cum += (int)(sizes[j] / 8192);
        }
        jobs.start[NJOBS] = cum;
        f2h_fused_k<<<cum, 256>>>(jobs);
    }
    transpose_h_k<<<dim3(32,32), dim3(32,8)>>>(ca_wk, ph_wkT);

    // 1. silu(t_emb) -> fp16
    silu_k<<<(BB*DD/2)/256, 256>>>(t_emb, ph_silu, BB*DD/2);

    // 2. mod = silu(t_emb) @ w_mod^T + b_mod   [1024, 9216] fp32
    GEMM_B(E_BIAS, O_F32)(ph_silu, ph_wmod, b_mod, pmod, nullptr,
                          BB, 9*DD, DD, DD, DD, 9*DD);

    // 3. m1 = ln(x)*(1+g1)+be1 -> fp16
    ln_mod_k<<<BB, 256>>>(x, pmod, 0*DD, 1*DD, ph_m);

    // 4. t1 = m1 @ sa_wv^T + sa_bv -> fp16
    GEMM_S(E_BIAS, O_F16)(ph_m, ph_sawv, sa_bv, nullptr, ph_t1,
                          BB, DD, DD, DD, DD, DD);

    // 5. x_q = x + a1 * (t1 @ sa_wo^T + sa_bo) -> fp32
    GEMM_S(E_RES, O_F32)(ph_t1, ph_sawo, sa_bo, pxq, nullptr,
                         BB, DD, DD, DD, DD, DD,
                         1, 0, 0, 0, 0, x, DD, pmod + 2*DD, 9*DD);

    // 6. m2 -> fp16
    ln_mod_k<<<BB, 256>>>(pxq, pmod, 3*DD, 4*DD, ph_m);

    // 7. q = (m2 @ ca_wq^T + ca_bq) / 8 -> fp32 + fp16
    GEMM_S(E_SCALE, O_BOTH)(ph_m, ph_cawq, ca_bq, pq, ph_q,
                            BB, DD, DD, DD, DD, DD,
                            1, 0, 0, 0, 0, nullptr, 0, nullptr, 0, 0.125f);

    // 8. qw[b,h,d] = sum_j q[b,h*64+j] * wkT[d,h*64+j]  (batched) -> fp32
    GEMM_S(E_BIAS, O_F32)(ph_q, ph_wkT, nullptr, pqw, nullptr,
                          BB, DD, DHH, DD, DD, HH*DD,
                          HH, DHH, DHH, 0, DD);

    // 9. attention (single-pass, cp.async distance-3 prefetch) -> ctxa fp16
    attn_k<<<BB, 512>>>(ctx, pqw, pq, ca_bk, ph_ctxa);

    // 10. ao = ctxa @ ca_wv^T + ca_bv  (batched heads) -> fp16
    GEMM_S(E_BIAS, O_F16)(ph_ctxa, ph_cawv, ca_bv, nullptr, ph_t1,
                          BB, DHH, DD, HH*DD, DD, DD,
                          HH, DD, (long)DHH*DD, DHH, DHH);

    // 11. x_q = x_q + a2 * (ao @ ca_wo^T + ca_bo) -> fp32
    GEMM_S(E_RES, O_F32)(ph_t1, ph_cawo, ca_bo, pxq, nullptr,
                         BB, DD, DD, DD, DD, DD,
                         1, 0, 0, 0, 0, pxq, DD, pmod + 5*DD, 9*DD);

    // 12. m3 -> fp16
    ln_mod_k<<<BB, 256>>>(pxq, pmod, 6*DD, 7*DD, ph_m);

    // 13. h1 = gelu(m3 @ w1^T + b1) -> fp16
    GEMM_B(E_GELU, O_F16)(ph_m, ph_w1, b1, nullptr, ph_h1,
                          BB, DFF, DD, DD, DD, DFF);

    // 14. h2 = gelu(h1 @ w2^T + b2) -> fp16
    GEMM_B(E_GELU, O_F16)(ph_h1, ph_w2, b2, nullptr, ph_h2,
                          BB, DFF, DFF, DFF, DFF, DFF);

    // 15. out = x_q + a3 * (h2 @ w3^T + b3) -> fp32
    GEMM_S(E_RES, O_F32)(ph_h2, ph_w3, b3, out, nullptr,
                         BB, DD, DFF, DFF, DFF, DD,
                         1, 0, 0, 0, 0, pxq, DD, pmod + 8*DD, 9*DD);
}